// round 17
// baseline (speedup 1.0000x reference)
#include <cuda_runtime.h>
#include <math.h>

#define L_TOTAL 32768
#define DMODEL  1024
#define NCHUNK  1024
#define L_PER   (L_TOTAL / NCHUNK)     // 32
#define GROUPS  64
#define CH_PER_G (NCHUNK / GROUPS)     // 16
#define THREADS1 128
#define ROWS_PER_BLK 8

// Scratch (allocation-free rule: __device__ globals)
__device__ float g_partials[NCHUNK * DMODEL];    // 4 MB
__device__ float g_partials2[GROUPS * DMODEL];   // 256 KB
__device__ float g_signal[DMODEL];               // 4 KB

// ---- packed f32x2 helpers (FFMA2 is PTX-only: fma.rn.f32x2) ----
__device__ __forceinline__ unsigned long long ffma2(
    unsigned long long a, unsigned long long b, unsigned long long c) {
    unsigned long long d;
    asm("fma.rn.f32x2 %0, %1, %2, %3;" : "=l"(d) : "l"(a), "l"(b), "l"(c));
    return d;
}
__device__ __forceinline__ unsigned long long pack2(float lo, float hi) {
    unsigned long long r;
    asm("mov.b64 %0, {%1, %2};" : "=l"(r) : "f"(lo), "f"(hi));
    return r;
}
__device__ __forceinline__ void unpack2(unsigned long long v, float& lo, float& hi) {
    asm("mov.b64 {%0, %1}, %2;" : "=f"(lo), "=f"(hi) : "l"(v));
}

// Kernel 1: partial sin-sums over a 32-position chunk of L, all 1024 d.
// 128 threads; each thread owns 8 d's (tid + 128k). Per (thread,l): one
// __sincosf seeds sin/cos at phase(d=tid); the 7 siblings come from FFMA2
// rotations with per-l precomputed {cosPsi_k, sinPsi_k} pairs. MUFU pipe:
// 2 instr / 8 outputs; FMA pipe: ~11 instr / 8 outputs -> ~3 cyc/output.
__global__ void __launch_bounds__(THREADS1)
sin_partial_kernel(const float* __restrict__ x) {
    // s_rot[l][p]: .x = pack(cosPsi_{2p}, cosPsi_{2p+1}), .y = pack(sinPsi_{2p}, sinPsi_{2p+1})
    __shared__ ulonglong2 s_rot[L_PER][4];
    __shared__ float2     s_ac[L_PER];          // (a, c) per l
    const int chunk = blockIdx.x;
    const int l0 = chunk * L_PER;
    const int tid = threadIdx.x;

    {   // prologue: 4 threads per l, each fills one rotation pair
        const int l = tid >> 2;                  // 0..31
        const int j = tid & 3;                   // pair index
        const float xv = x[l0 + l];
        const float a  = 6.28318530717958647692f * xv;      // 2*pi*x[l]
        const float dt = 128.0f / 1023.0f;                  // d-stride in t
        const int k1 = 2 * j + 1;
        float sLo, cLo, sHi, cHi;
        __sincosf(a * (dt * (float)k1), &sHi, &cHi);
        if (j != 0) {
            __sincosf(a * (dt * (float)(2 * j)), &sLo, &cLo);
        } else {
            sLo = 0.0f; cLo = 1.0f;              // Psi_0 = 0
        }
        s_rot[l][j].x = pack2(cLo, cHi);
        s_rot[l][j].y = pack2(sLo, sHi);
        if (j == 0) {
            const float p = logf(1.0f + (float)(l0 + l));   // log1p(l)
            s_ac[l] = make_float2(a, a * p);
        }
    }
    __syncthreads();

    const float t0 = (float)tid * (1.0f / 1023.0f);

    unsigned long long acc01 = 0ull, acc23 = 0ull, acc45 = 0ull, acc67 = 0ull;

    #pragma unroll 8
    for (int l = 0; l < L_PER; ++l) {
        const float2 ac = s_ac[l];                 // warp-uniform broadcast
        const float ph = fmaf(ac.x, t0, ac.y);
        float s, c;
        __sincosf(ph, &s, &c);                     // 2 MUFU
        const unsigned long long s2 = pack2(s, s);
        const unsigned long long c2 = pack2(c, c);
        const ulonglong2 r0 = s_rot[l][0];
        const ulonglong2 r1 = s_rot[l][1];
        const ulonglong2 r2 = s_rot[l][2];
        const ulonglong2 r3 = s_rot[l][3];
        acc01 = ffma2(s2, r0.x, acc01);  acc01 = ffma2(c2, r0.y, acc01);
        acc23 = ffma2(s2, r1.x, acc23);  acc23 = ffma2(c2, r1.y, acc23);
        acc45 = ffma2(s2, r2.x, acc45);  acc45 = ffma2(c2, r2.y, acc45);
        acc67 = ffma2(s2, r3.x, acc67);  acc67 = ffma2(c2, r3.y, acc67);
    }

    float a0,a1,a2,a3,a4,a5,a6,a7;
    unpack2(acc01, a0, a1);
    unpack2(acc23, a2, a3);
    unpack2(acc45, a4, a5);
    unpack2(acc67, a6, a7);

    float* out = g_partials + chunk * DMODEL;
    out[tid          ] = a0;
    out[tid + 128    ] = a1;
    out[tid + 128 * 2] = a2;
    out[tid + 128 * 3] = a3;
    out[tid + 128 * 4] = a4;
    out[tid + 128 * 5] = a5;
    out[tid + 128 * 6] = a6;
    out[tid + 128 * 7] = a7;
}

// Kernel 2 (stage 1): sum 16 chunks per group. grid=(4,64)=256 blocks.
// Coalesced across threads, deterministic fixed order per output. MLP=16.
__global__ void __launch_bounds__(256)
reduce1_kernel() {
    const int d = blockIdx.x * 256 + threadIdx.x;
    const int g = blockIdx.y;
    const float* src = g_partials + (g * CH_PER_G) * DMODEL + d;
    float s = 0.f;
    #pragma unroll
    for (int c = 0; c < CH_PER_G; ++c)
        s += src[c * DMODEL];
    g_partials2[g * DMODEL + d] = s;
}

// Kernel 3 (stage 2): 4 blocks x 256 -> g_signal[1024]. 256KB from L2, MLP=64.
__global__ void __launch_bounds__(256)
reduce2_kernel() {
    const int d = blockIdx.x * 256 + threadIdx.x;
    float s = 0.f;
    #pragma unroll
    for (int g = 0; g < GROUPS; ++g)
        s += g_partials2[g * DMODEL + d];
    g_signal[d] = s;
}

// Kernel 4: matvec, 8 rows per block (128 blocks). Each thread loads its
// signal float4 once, then 8 independent W float4 loads (MLP=8), producing
// 8 row-partials -> smem -> one warp per row does a fixed-order tree
// reduction (deterministic).
__global__ void __launch_bounds__(256)
matvec_kernel(const float* __restrict__ W, const float* __restrict__ b,
              float* __restrict__ out) {
    __shared__ float sp[ROWS_PER_BLK][256];
    const int tid  = threadIdx.x;
    const int row0 = blockIdx.x * ROWS_PER_BLK;

    const float4 s4 = ((const float4*)g_signal)[tid];

    float4 w4[ROWS_PER_BLK];
    #pragma unroll
    for (int r = 0; r < ROWS_PER_BLK; ++r)
        w4[r] = ((const float4*)(W + (row0 + r) * DMODEL))[tid];   // MLP=8

    #pragma unroll
    for (int r = 0; r < ROWS_PER_BLK; ++r) {
        float s = w4[r].x * s4.x;
        s = fmaf(w4[r].y, s4.y, s);
        s = fmaf(w4[r].z, s4.z, s);
        s = fmaf(w4[r].w, s4.w, s);
        sp[r][tid] = s;
    }
    __syncthreads();

    const int warp = tid >> 5;      // warp r reduces row r
    const int lane = tid & 31;
    {
        const float* p = sp[warp];
        float s = p[lane];
        #pragma unroll
        for (int k = 1; k < 8; ++k)           // 256 values, fixed order
            s += p[k * 32 + lane];
        #pragma unroll
        for (int o = 16; o > 0; o >>= 1)
            s += __shfl_down_sync(0xffffffffu, s, o);
        if (lane == 0)
            out[row0 + warp] = s + b[row0 + warp];
    }
}

extern "C" void kernel_launch(void* const* d_in, const int* in_sizes, int n_in,
                              void* d_out, int out_size) {
    const float* x = (const float*)d_in[0];   // inputs [32768]
    const float* W = (const float*)d_in[1];   // W [1024,1024] row-major
    const float* b = (const float*)d_in[2];   // b [1024]
    float* out = (float*)d_out;               // [1024] float32

    sin_partial_kernel<<<NCHUNK, THREADS1>>>(x);

    dim3 rgrid(DMODEL / 256, GROUPS);
    reduce1_kernel<<<rgrid, 256>>>();
    reduce2_kernel<<<4, 256>>>();

    matvec_kernel<<<DMODEL / ROWS_PER_BLK, 256>>>(W, b, out);
}